// round 17
// baseline (speedup 1.0000x reference)
#include <cuda_runtime.h>

#define BB 2
#define NN 512
#define DM 256
#define HH 8
#define HD 32
#define HF 16
#define TQ 4          // query rows per block
#define MT 64         // key rows per tile
#define NT (NN/MT)    // 8 tiles
#define KP 260        // sK row pitch
#define XP 25         // sXm row pitch
#define SCALE 0.17677669529663687f
#define LOG2E 1.4426950408889634f

__device__ float g_Q[BB*NN*DM];
__device__ float g_K[BB*NN*DM];
__device__ float g_V[BB*NN*DM];
__device__ float g_ctx[BB*NN*DM];

__constant__ float cFREQ[HF] = {
    1.0f, 0.5623413251903491f, 0.31622776601683794f, 0.17782794100389228f,
    0.1f, 0.05623413251903491f, 0.031622776601683794f, 0.017782794100389228f,
    0.01f, 0.005623413251903491f, 0.0031622776601683794f, 0.0017782794100389228f,
    0.001f, 0.0005623413251903491f, 0.00031622776601683794f, 0.00017782794100389228f };

__device__ __forceinline__ float ex2(float x) {
    float r; asm("ex2.approx.ftz.f32 %0, %1;" : "=f"(r) : "f"(x)); return r;
}

// ---- cp.async helpers -------------------------------------------------------
__device__ __forceinline__ void cpa16(void* smem_ptr, const void* gptr) {
    unsigned sa = (unsigned)__cvta_generic_to_shared(smem_ptr);
    asm volatile("cp.async.cg.shared.global [%0], [%1], 16;\n" :: "r"(sa), "l"(gptr) : "memory");
}
__device__ __forceinline__ void cpa_commit() {
    asm volatile("cp.async.commit_group;\n" ::: "memory");
}
__device__ __forceinline__ void cpa_wait0() {
    asm volatile("cp.async.wait_group 0;\n" ::: "memory");
}

// ---------------------------------------------------------------------------
// k-major staged GEMM, double-buffered smem. [R6-verified]
// block = 128 threads, tile 32 rows x 64 cols, thread tile 4x4.
// ---------------------------------------------------------------------------
__device__ __forceinline__ void gemm32(const float* __restrict__ A,
                                       const float* __restrict__ W,
                                       const float* __restrict__ bias,
                                       float* __restrict__ O)
{
    __shared__ __align__(16) float sA[2][16][36];
    __shared__ __align__(16) float sW[2][16][68];
    const int tid = threadIdx.x;
    const int r0 = blockIdx.x * 32, c0 = blockIdx.y * 64;
    const int ty = tid >> 4, tx = tid & 15;

    float acc[4][4];
#pragma unroll
    for (int i = 0; i < 4; ++i)
#pragma unroll
        for (int j = 0; j < 4; ++j) acc[i][j] = 0.f;

    const int arow = tid >> 2, ako = (tid & 3) << 2;
    const int wrow = tid >> 1, wko = (tid & 1) << 3;

    const float* ap = A + (r0 + arow) * DM + ako;
    const float* wp = W + (c0 + wrow) * DM + wko;

    {
        float4 pa  = *(const float4*)(ap);
        float4 pw0 = *(const float4*)(wp);
        float4 pw1 = *(const float4*)(wp + 4);
        sA[0][ako+0][arow] = pa.x; sA[0][ako+1][arow] = pa.y;
        sA[0][ako+2][arow] = pa.z; sA[0][ako+3][arow] = pa.w;
        sW[0][wko+0][wrow] = pw0.x; sW[0][wko+1][wrow] = pw0.y;
        sW[0][wko+2][wrow] = pw0.z; sW[0][wko+3][wrow] = pw0.w;
        sW[0][wko+4][wrow] = pw1.x; sW[0][wko+5][wrow] = pw1.y;
        sW[0][wko+6][wrow] = pw1.z; sW[0][wko+7][wrow] = pw1.w;
    }
    __syncthreads();

    int buf = 0;
    for (int k0 = 0; k0 < DM; k0 += 16, buf ^= 1) {
        const bool has_next = (k0 + 16 < DM);
        float4 pa, pw0, pw1;
        if (has_next) {
            pa  = *(const float4*)(ap + k0 + 16);
            pw0 = *(const float4*)(wp + k0 + 16);
            pw1 = *(const float4*)(wp + k0 + 20);
        }
#pragma unroll
        for (int k = 0; k < 16; ++k) {
            float4 av = *(const float4*)&sA[buf][k][ty*4];
            float4 wv = *(const float4*)&sW[buf][k][tx*4];
            acc[0][0] = fmaf(av.x, wv.x, acc[0][0]);
            acc[0][1] = fmaf(av.x, wv.y, acc[0][1]);
            acc[0][2] = fmaf(av.x, wv.z, acc[0][2]);
            acc[0][3] = fmaf(av.x, wv.w, acc[0][3]);
            acc[1][0] = fmaf(av.y, wv.x, acc[1][0]);
            acc[1][1] = fmaf(av.y, wv.y, acc[1][1]);
            acc[1][2] = fmaf(av.y, wv.z, acc[1][2]);
            acc[1][3] = fmaf(av.y, wv.w, acc[1][3]);
            acc[2][0] = fmaf(av.z, wv.x, acc[2][0]);
            acc[2][1] = fmaf(av.z, wv.y, acc[2][1]);
            acc[2][2] = fmaf(av.z, wv.z, acc[2][2]);
            acc[2][3] = fmaf(av.z, wv.w, acc[2][3]);
            acc[3][0] = fmaf(av.w, wv.x, acc[3][0]);
            acc[3][1] = fmaf(av.w, wv.y, acc[3][1]);
            acc[3][2] = fmaf(av.w, wv.z, acc[3][2]);
            acc[3][3] = fmaf(av.w, wv.w, acc[3][3]);
        }
        if (has_next) {
            int nb = buf ^ 1;
            sA[nb][ako+0][arow] = pa.x; sA[nb][ako+1][arow] = pa.y;
            sA[nb][ako+2][arow] = pa.z; sA[nb][ako+3][arow] = pa.w;
            sW[nb][wko+0][wrow] = pw0.x; sW[nb][wko+1][wrow] = pw0.y;
            sW[nb][wko+2][wrow] = pw0.z; sW[nb][wko+3][wrow] = pw0.w;
            sW[nb][wko+4][wrow] = pw1.x; sW[nb][wko+5][wrow] = pw1.y;
            sW[nb][wko+6][wrow] = pw1.z; sW[nb][wko+7][wrow] = pw1.w;
        }
        __syncthreads();
    }
    float4 bv = *(const float4*)(bias + c0 + tx*4);
#pragma unroll
    for (int i = 0; i < 4; ++i) {
        float4 o = make_float4(acc[i][0]+bv.x, acc[i][1]+bv.y,
                               acc[i][2]+bv.z, acc[i][3]+bv.w);
        *(float4*)(O + (r0 + ty*4 + i) * DM + c0 + tx*4) = o;
    }
}

__global__ void __launch_bounds__(128) k_qkv(const float* __restrict__ h,
                                             const float* __restrict__ Wq,
                                             const float* __restrict__ Wk,
                                             const float* __restrict__ Wv,
                                             const float* __restrict__ bq,
                                             const float* __restrict__ bk,
                                             const float* __restrict__ bv)
{
    const int z = blockIdx.z;
    const float* W = (z == 0) ? Wq : (z == 1) ? Wk : Wv;
    const float* b = (z == 0) ? bq : (z == 1) ? bk : bv;
    float* O = (z == 0) ? g_Q : (z == 1) ? g_K : g_V;
    gemm32(h, W, b, O);
}

__global__ void __launch_bounds__(128) k_out(const float* __restrict__ Wo,
                                             const float* __restrict__ bo,
                                             float* __restrict__ out)
{
    gemm32(g_ctx, Wo, bo, out);
}

// ---------------------------------------------------------------------------
// Fused attention (R16 champion) with PV unroll 16 and EB prefetch.
// grid: (NN/TQ, BB) = (128, 2), block: 256 threads
// ---------------------------------------------------------------------------
__global__ void __launch_bounds__(256, 2) k_attn(const float* __restrict__ X,
                                                 const float* __restrict__ EB,
                                                 const float* __restrict__ WKER,
                                                 const float* __restrict__ BETA)
{
    extern __shared__ __align__(16) float smem[];
    float* sK    = smem;                 // 64*260
    float* sQ    = sK + MT*KP;           // 4*256
    float* sS    = sQ + TQ*DM;           // 4*8*64
    float* sXm   = sS + TQ*HH*MT;        // 64*25
    float* sCoef = sXm + MT*XP;          // 8*4

    const int b   = blockIdx.y;
    const int n0  = blockIdx.x * TQ;
    const int tid = threadIdx.x;

    const int qA = tid >> 6, mlA = tid & 63;   // phase A identity
    const int hB = tid >> 5, dB  = tid & 31;   // phase B identity

    const float* kgb = g_K + b*NN*DM;
    const float* xgb = X + b*NN*24;
    const float* ebp = EB + (b*NN + n0 + qA)*NN + mlA;   // per-thread EB stream

    int krow[16], kcol[16];
#pragma unroll
    for (int i = 0; i < 16; ++i) { int idx = tid + 256*i; krow[i] = idx >> 6; kcol[i] = idx & 63; }

    // ---- block setup ----
    {
        int q = tid >> 6, i = tid & 63;
        ((float4*)sQ)[tid] = ((const float4*)(g_Q + (b*NN + n0 + q)*DM))[i];
    }
    if (tid < HH*3) {
        int hh = tid/3, c = tid%3;
        float w = WKER[hh*3+c] * BETA[hh] * LOG2E;   // fold log2e
        sCoef[hh*4+c] = (c == 1) ? w : -w;           // [-dh, +sdot, -de2]
    }
    {
        const float* xg = xgb;
#pragma unroll
        for (int i = 0; i < 6; ++i) {
            int idx = tid + 256*i;
            int row = idx / 24, c = idx - row*24;
            sXm[row*XP + c] = xg[idx];
        }
    }
    {
        const float* kg = kgb;
#pragma unroll
        for (int i = 0; i < 16; ++i)
            cpa16(&sK[krow[i]*KP + kcol[i]*4], kg + krow[i]*DM + kcol[i]*4);
        cpa_commit();
    }

    float xq[24];
    {
        const float* xp = X + (b*NN + n0 + qA)*24;
#pragma unroll
        for (int j = 0; j < 24; ++j) xq[j] = xp[j];
    }
    float oneq = 1.0f;
#pragma unroll
    for (int j = 0; j < 8; ++j) oneq = fmaf(-xq[j], xq[j], oneq);

    float Ssum[TQ], acc[TQ];
#pragma unroll
    for (int q = 0; q < TQ; ++q) { Ssum[q] = 0.f; acc[q] = 0.f; }

    float ebv = ebp[0];   // EB for tile 0

    cpa_wait0();
    __syncthreads();

    for (int t = 0; t < NT; ++t) {
        // ---- Phase A: geometry + RoPE scores -> p = 2^sc ----
        {
            const float* xm = &sXm[mlA*XP];
            float dh2 = 0.f, om = 1.0f, sd = 0.f, de2 = 0.f;
#pragma unroll
            for (int j = 0; j < 8; ++j) {
                float c = xm[j];
                float d = xq[j] - c;
                dh2 = fmaf(d, d, dh2);
                om  = fmaf(-c, c, om);
            }
#pragma unroll
            for (int j = 0; j < 8; ++j) sd = fmaf(xq[8+j], xm[8+j], sd);
#pragma unroll
            for (int j = 0; j < 8; ++j) {
                float d = xq[16+j] - xm[16+j];
                de2 = fmaf(d, d, de2);
            }
            float tt = fmaxf(2.0f * dh2 / (oneq * om), 1e-6f);
            float dh = __logf(1.0f + tt + sqrtf(tt * (tt + 2.0f)));
            float sdc = fminf(fmaxf(sd, -1.0f + 1e-6f), 1.0f - 1e-6f);
            float ds = acosf(sdc);
            float dist = sqrtf(fmaf(dh, dh, fmaf(ds, ds, de2)));

            float cs[HF], sn[HF];
#pragma unroll
            for (int f = 0; f < HF; ++f) __sincosf(dist * cFREQ[f], &sn[f], &cs[f]);

            const float ebl = ebv * LOG2E;
            const float* krowp = &sK[mlA*KP];

#pragma unroll
            for (int hh = 0; hh < HH; ++hh) {
                const float4* kq = (const float4*)(krowp + hh*HD);
                const float4* qq = (const float4*)(sQ + qA*DM + hh*HD);
                float sa = 0.f, sb = 0.f;
#pragma unroll
                for (int f4 = 0; f4 < 8; ++f4) {
                    float4 kv = kq[f4];
                    float4 qv = qq[f4];
                    const int f0 = f4*2;
                    float same0 = fmaf(qv.x, kv.x, qv.y*kv.y);
                    float crs0  = fmaf(qv.x, kv.y, -qv.y*kv.x);
                    sa = fmaf(cs[f0], same0, sa);
                    sb = fmaf(sn[f0], crs0,  sb);
                    float same1 = fmaf(qv.z, kv.z, qv.w*kv.w);
                    float crs1  = fmaf(qv.z, kv.w, -qv.w*kv.z);
                    sa = fmaf(cs[f0+1], same1, sa);
                    sb = fmaf(sn[f0+1], crs1,  sb);
                }
                float sc = fmaf(sa + sb, SCALE * LOG2E, ebl);
                sc = fmaf(sCoef[hh*4+0], dh,  sc);
                sc = fmaf(sCoef[hh*4+1], sd,  sc);
                sc = fmaf(sCoef[hh*4+2], de2, sc);
                sS[(qA*HH + hh)*MT + mlA] = ex2(sc);
            }
        }
        __syncthreads();   // sS(p) ready; sK/sXm free for restage

        // ---- restage next tile (overlaps phase B) + EB prefetch ----
        if (t + 1 < NT) {
            ebv = ebp[(t+1)*MT];   // prefetch next tile's edge bias
            const float* kg = kgb + (t+1)*MT*DM;
#pragma unroll
            for (int i = 0; i < 16; ++i)
                cpa16(&sK[krow[i]*KP + kcol[i]*4], kg + krow[i]*DM + kcol[i]*4);
            cpa_commit();
            const float* xg = xgb + (t+1)*MT*24;
#pragma unroll
            for (int i = 0; i < 6; ++i) {
                int idx = tid + 256*i;
                int row = idx / 24, c = idx - row*24;
                sXm[row*XP + c] = xg[idx];
            }
        }

        // ---- Phase B: normalizer sum (read-only) + PV (unroll 16 for MLP) ----
        {
#pragma unroll
            for (int q = 0; q < TQ; ++q) {
                const float* srow = &sS[(q*HH + hB)*MT];
                Ssum[q] += srow[dB] + srow[dB + 32];
            }
            const float* vb = g_V + (b*NN + t*MT)*DM + hB*HD + dB;
#pragma unroll
            for (int m16 = 0; m16 < MT/16; ++m16) {
                float v[16];
#pragma unroll
                for (int i = 0; i < 16; ++i) v[i] = vb[(m16*16 + i)*DM];
#pragma unroll
                for (int q = 0; q < TQ; ++q) {
                    const float* srow = &sS[(q*HH + hB)*MT + m16*16];
                    float4 p0 = *(const float4*)(srow);
                    float4 p1 = *(const float4*)(srow + 4);
                    float4 p2 = *(const float4*)(srow + 8);
                    float4 p3 = *(const float4*)(srow + 12);
                    float a = acc[q];
                    a = fmaf(p0.x, v[0],  a);
                    a = fmaf(p0.y, v[1],  a);
                    a = fmaf(p0.z, v[2],  a);
                    a = fmaf(p0.w, v[3],  a);
                    a = fmaf(p1.x, v[4],  a);
                    a = fmaf(p1.y, v[5],  a);
                    a = fmaf(p1.z, v[6],  a);
                    a = fmaf(p1.w, v[7],  a);
                    a = fmaf(p2.x, v[8],  a);
                    a = fmaf(p2.y, v[9],  a);
                    a = fmaf(p2.z, v[10], a);
                    a = fmaf(p2.w, v[11], a);
                    a = fmaf(p3.x, v[12], a);
                    a = fmaf(p3.y, v[13], a);
                    a = fmaf(p3.z, v[14], a);
                    a = fmaf(p3.w, v[15], a);
                    acc[q] = a;
                }
            }
        }
        cpa_wait0();
        __syncthreads();
    }

    // ---- final: reduce normalizer once, write out ----
#pragma unroll
    for (int q = 0; q < TQ; ++q) {
        float s = Ssum[q];
#pragma unroll
        for (int o = 16; o; o >>= 1) s += __shfl_xor_sync(0xffffffffu, s, o);
        g_ctx[(b*NN + n0 + q)*DM + tid] = acc[q] * (1.0f / s);
    }
}

// ---------------------------------------------------------------------------
extern "C" void kernel_launch(void* const* d_in, const int* in_sizes, int n_in,
                              void* d_out, int out_size)
{
    (void)in_sizes; (void)n_in; (void)out_size;
    const float* h    = (const float*)d_in[0];
    const float* x    = (const float*)d_in[1];
    const float* Wq   = (const float*)d_in[2];
    const float* bq   = (const float*)d_in[3];
    const float* Wk   = (const float*)d_in[4];
    const float* bk   = (const float*)d_in[5];
    const float* Wv   = (const float*)d_in[6];
    const float* bv   = (const float*)d_in[7];
    const float* Wo   = (const float*)d_in[8];
    const float* bo   = (const float*)d_in[9];
    const float* wker = (const float*)d_in[10];
    const float* beta = (const float*)d_in[11];
    const float* eb   = (const float*)d_in[12];
    float* out = (float*)d_out;

    const int smem_attn = (MT*KP + TQ*DM + TQ*HH*MT + MT*XP + HH*4) * (int)sizeof(float);
    static int attr_set = 0;
    if (!attr_set) {
        cudaFuncSetAttribute(k_attn, cudaFuncAttributeMaxDynamicSharedMemorySize, smem_attn);
        attr_set = 1;
    }

    k_qkv<<<dim3((BB*NN)/32, DM/64, 3), 128>>>(h, Wq, Wk, Wv, bq, bk, bv);
    k_attn<<<dim3(NN/TQ, BB), 256, smem_attn>>>(x, eb, wker, beta);
    k_out<<<dim3((BB*NN)/32, DM/64), 128>>>(Wo, bo, out);
}